// round 2
// baseline (speedup 1.0000x reference)
#include <cuda_runtime.h>

// ---------------------------------------------------------------------------
// DoG 3D: out = blur(x, sigma=1.0, k=9) - blur(x, sigma=1.6, k=15)
// Separable; each 1D pass uses replicate (edge-clamp) boundary.
// 3 fused passes: W (both filters), H (both), D (both + subtract).
// ---------------------------------------------------------------------------

#define NB 2
#define L 160
#define SLAB (L * L)          // 25600
#define VOL (L * L * L)       // 4096000
#define TOT (NB * VOL)        // 8192000

// Static scratch (allocation-free rule): ping-pong low/high buffers.
__device__ float g_loA[TOT];
__device__ float g_hiA[TOT];
__device__ float g_loB[TOT];
__device__ float g_hiB[TOT];

// Precomputed normalized 1D gaussian weights (sum == 1).
// low: ksize=9, sigma=1.0 ; high: ksize=15, sigma=1.6
__device__ __constant__ const float KLW[9] = {
    1.338302e-04f, 4.431861e-03f, 5.399113e-02f, 2.419714e-01f,
    3.989435e-01f,
    2.419714e-01f, 5.399113e-02f, 4.431861e-03f, 1.338302e-04f
};
__device__ __constant__ const float KHW[15] = {
    1.739620e-05f, 2.203730e-04f, 1.888900e-03f, 1.095520e-02f,
    4.299160e-02f, 1.141557e-01f, 2.051009e-01f,
    2.493392e-01f,
    2.051009e-01f, 1.141557e-01f, 4.299160e-02f, 1.095520e-02f,
    1.888900e-03f, 2.203730e-04f, 1.739620e-05f
};

// Compile-time copies so unrolled loops fold to FFMA with immediate operands.
#define KL0 1.338302e-04f
#define KL1 4.431861e-03f
#define KL2 5.399113e-02f
#define KL3 2.419714e-01f
#define KL4 3.989435e-01f

#define KH0 1.739620e-05f
#define KH1 2.203730e-04f
#define KH2 1.888900e-03f
#define KH3 1.095520e-02f
#define KH4 4.299160e-02f
#define KH5 1.141557e-01f
#define KH6 2.051009e-01f
#define KH7 2.493392e-01f

__device__ __forceinline__ float klw(int i) {
    // i in 0..8, symmetric
    const float v[9] = {KL0, KL1, KL2, KL3, KL4, KL3, KL2, KL1, KL0};
    return v[i];
}
__device__ __forceinline__ float khw(int i) {
    // i in 0..14, symmetric
    const float v[15] = {KH0, KH1, KH2, KH3, KH4, KH5, KH6, KH7,
                         KH6, KH5, KH4, KH3, KH2, KH1, KH0};
    return v[i];
}

// ---------------- pass 1: conv along W (stride-1 axis) ---------------------
// One block row-group: 4 rows of 160, smem tile, clamped smem reads.
__global__ void __launch_bounds__(640) pass_w_kernel(const float* __restrict__ x) {
    __shared__ float s[4][L];
    const int w = threadIdx.x;                       // 0..159
    const int ry = threadIdx.y;                      // 0..3
    const int row = blockIdx.x * 4 + ry;             // 0..51199
    const int base = row * L;

    s[ry][w] = x[base + w];
    __syncthreads();

    float sL = 0.f, sH = 0.f;
#pragma unroll
    for (int t = -7; t <= 7; ++t) {
        int ww = w + t;
        ww = ww < 0 ? 0 : (ww > (L - 1) ? (L - 1) : ww);
        const float u = s[ry][ww];
        sH = fmaf(u, khw(t + 7), sH);
        if (t >= -4 && t <= 4) sL = fmaf(u, klw(t + 4), sL);
    }
    g_loA[base + w] = sL;
    g_hiA[base + w] = sH;
}

// ---------------- pass 2: conv along H (stride L) --------------------------
// Register-blocked: each thread owns (n,d,w, 16-high segment).
__global__ void __launch_bounds__(256) pass_h_kernel() {
    const int tid = blockIdx.x * 256 + threadIdx.x;  // < 512000
    const int w = tid % L;
    const int r = tid / L;        // 0..3199
    const int seg = r % 10;
    const int nd = r / 10;        // n*160+d, 0..319
    const int base = nd * SLAB + w;
    const int h0 = seg * 16;

    float aH[30], aL[24];
#pragma unroll
    for (int j = 0; j < 30; ++j) {
        int h = h0 + j - 7;
        h = h < 0 ? 0 : (h > (L - 1) ? (L - 1) : h);
        aH[j] = g_hiA[base + h * L];
    }
#pragma unroll
    for (int j = 0; j < 24; ++j) {
        int h = h0 + j - 4;
        h = h < 0 ? 0 : (h > (L - 1) ? (L - 1) : h);
        aL[j] = g_loA[base + h * L];
    }
#pragma unroll
    for (int i = 0; i < 16; ++i) {
        float sL = 0.f, sH = 0.f;
#pragma unroll
        for (int t = 0; t < 9; ++t) sL = fmaf(aL[i + t], klw(t), sL);
#pragma unroll
        for (int t = 0; t < 15; ++t) sH = fmaf(aH[i + t], khw(t), sH);
        const int o = base + (h0 + i) * L;
        g_loB[o] = sL;
        g_hiB[o] = sH;
    }
}

// ---------------- pass 3: conv along D (stride L*L) + subtract -------------
__global__ void __launch_bounds__(256) pass_d_kernel(float* __restrict__ out) {
    const int tid = blockIdx.x * 256 + threadIdx.x;  // < 512000
    const int w = tid % L;
    const int q = tid / L;        // 0..3199
    const int h = q % L;
    const int q2 = q / L;         // 0..19
    const int seg = q2 % 10;
    const int n = q2 / 10;        // 0..1
    const int base = n * VOL + h * L + w;
    const int d0 = seg * 16;

    float aH[30], aL[24];
#pragma unroll
    for (int j = 0; j < 30; ++j) {
        int d = d0 + j - 7;
        d = d < 0 ? 0 : (d > (L - 1) ? (L - 1) : d);
        aH[j] = g_hiB[base + d * SLAB];
    }
#pragma unroll
    for (int j = 0; j < 24; ++j) {
        int d = d0 + j - 4;
        d = d < 0 ? 0 : (d > (L - 1) ? (L - 1) : d);
        aL[j] = g_loB[base + d * SLAB];
    }
#pragma unroll
    for (int i = 0; i < 16; ++i) {
        float sL = 0.f, sH = 0.f;
#pragma unroll
        for (int t = 0; t < 9; ++t) sL = fmaf(aL[i + t], klw(t), sL);
#pragma unroll
        for (int t = 0; t < 15; ++t) sH = fmaf(aH[i + t], khw(t), sH);
        out[base + (d0 + i) * SLAB] = sL - sH;
    }
}

extern "C" void kernel_launch(void* const* d_in, const int* in_sizes, int n_in,
                              void* d_out, int out_size) {
    const float* x = (const float*)d_in[0];
    float* out = (float*)d_out;

    // rows = 2*160*160 = 51200; 4 rows/block
    pass_w_kernel<<<51200 / 4, dim3(160, 4)>>>(x);
    // 512000 threads, 256/block
    pass_h_kernel<<<2000, 256>>>();
    pass_d_kernel<<<2000, 256>>>(out);
}

// round 3
// speedup vs baseline: 1.2439x; 1.2439x over previous
#include <cuda_runtime.h>

// ---------------------------------------------------------------------------
// DoG 3D: out = blur(x, sigma=1.0, k=9) - blur(x, sigma=1.6, k=15)
// Separable, replicate boundary. 2 kernels:
//   fused W+H pass (smem 2D tile)  ->  g_loB, g_hiB
//   D pass + subtract              ->  out
// ---------------------------------------------------------------------------

#define NB 2
#define L 160
#define SLAB (L * L)          // 25600
#define VOL (L * L * L)       // 4096000
#define TOT (NB * VOL)        // 8192000

__device__ float g_loB[TOT];
__device__ float g_hiB[TOT];

// Normalized 1D gaussian weights (each sums to 1).
#define KL0 1.338302e-04f
#define KL1 4.431861e-03f
#define KL2 5.399113e-02f
#define KL3 2.419714e-01f
#define KL4 3.989435e-01f

#define KH0 1.739620e-05f
#define KH1 2.203730e-04f
#define KH2 1.888900e-03f
#define KH3 1.095520e-02f
#define KH4 4.299160e-02f
#define KH5 1.141557e-01f
#define KH6 2.051009e-01f
#define KH7 2.493392e-01f

__device__ __forceinline__ float klw(int i) {
    const float v[9] = {KL0, KL1, KL2, KL3, KL4, KL3, KL2, KL1, KL0};
    return v[i];
}
__device__ __forceinline__ float khw(int i) {
    const float v[15] = {KH0, KH1, KH2, KH3, KH4, KH5, KH6, KH7,
                         KH6, KH5, KH4, KH3, KH2, KH1, KH0};
    return v[i];
}

// ---------------- fused pass: conv along W then H ---------------------------
// Grid: 320 slabs (n*160+d) x 5 h-tiles. Block: 320 threads.
// smem: input  [46][176]  (rows = h0-7..h0+38 clamped, cols = w -7..166 clamped)
//       wlo/whi[46][160]  (W-convolved planes)
#define HT 32
#define ROWS (HT + 14)        // 46
#define PADW 176              // 160 + 14 halo, padded to 176

__global__ void __launch_bounds__(320, 2) pass_wh_kernel(const float* __restrict__ x) {
    extern __shared__ float sm[];
    float* s_in = sm;                      // ROWS * PADW
    float* s_lo = sm + ROWS * PADW;        // ROWS * L
    float* s_hi = s_lo + ROWS * L;         // ROWS * L

    const int b = blockIdx.x;
    const int slab = b / 5;                // 0..319  (n*160 + d)
    const int tile = b % 5;
    const int h0 = tile * HT - 7;          // first loaded (unclamped) row
    const int base_g = slab * SLAB;
    const int tid = threadIdx.x;

    // ---- load input tile with replicate clamp in h and w -------------------
    for (int idx = tid; idx < ROWS * 174; idx += 320) {
        const int r = idx / 174;
        const int c = idx % 174;           // c-7 = w
        int h = h0 + r;
        h = h < 0 ? 0 : (h > (L - 1) ? (L - 1) : h);
        int w = c - 7;
        w = w < 0 ? 0 : (w > (L - 1) ? (L - 1) : w);
        s_in[r * PADW + c] = x[base_g + h * L + w];
    }
    __syncthreads();

    // ---- W-conv: warp per row, lane computes 5 consecutive outputs ---------
    {
        const int warp = tid >> 5;
        const int lane = tid & 31;
        const int c0 = lane * 5;           // output w = c0..c0+4
        for (int r = warp; r < ROWS; r += 10) {
            const float* row = &s_in[r * PADW];
            float v[19];
#pragma unroll
            for (int j = 0; j < 19; ++j) v[j] = row[c0 + j];
#pragma unroll
            for (int o = 0; o < 5; ++o) {
                float sH = 0.f, sL = 0.f;
#pragma unroll
                for (int t = 0; t < 15; ++t) sH = fmaf(v[o + t], khw(t), sH);
#pragma unroll
                for (int t = 0; t < 9; ++t)  sL = fmaf(v[o + t + 3], klw(t), sL);
                s_lo[r * L + c0 + o] = sL;
                s_hi[r * L + c0 + o] = sH;
            }
        }
    }
    __syncthreads();

    // ---- H-conv: w = tid%160, each thread does 16 h outputs ----------------
    {
        const int w = tid % L;
        const int hh0 = (tid / L) * 16;    // 0 or 16 (local output h base)

        float bH[30];
#pragma unroll
        for (int j = 0; j < 30; ++j) bH[j] = s_hi[(hh0 + j) * L + w];
        float aL[24];
#pragma unroll
        for (int j = 0; j < 24; ++j) aL[j] = s_lo[(hh0 + j + 3) * L + w];

#pragma unroll
        for (int i = 0; i < 16; ++i) {
            float sH = 0.f, sL = 0.f;
#pragma unroll
            for (int t = 0; t < 15; ++t) sH = fmaf(bH[i + t], khw(t), sH);
#pragma unroll
            for (int t = 0; t < 9; ++t)  sL = fmaf(aL[i + t], klw(t), sL);
            const int gh = tile * HT + hh0 + i;
            const int o = base_g + gh * L + w;
            g_loB[o] = sL;
            g_hiB[o] = sH;
        }
    }
}

// ---------------- pass D: conv along D (stride L*L) + subtract -------------
__global__ void __launch_bounds__(256) pass_d_kernel(float* __restrict__ out) {
    const int tid = blockIdx.x * 256 + threadIdx.x;  // < 512000
    const int w = tid % L;
    const int q = tid / L;        // 0..3199
    const int h = q % L;
    const int q2 = q / L;         // 0..19
    const int seg = q2 % 10;
    const int n = q2 / 10;        // 0..1
    const int base = n * VOL + h * L + w;
    const int d0 = seg * 16;

    float aH[30], aL[24];
#pragma unroll
    for (int j = 0; j < 30; ++j) {
        int d = d0 + j - 7;
        d = d < 0 ? 0 : (d > (L - 1) ? (L - 1) : d);
        aH[j] = g_hiB[base + d * SLAB];
    }
#pragma unroll
    for (int j = 0; j < 24; ++j) {
        int d = d0 + j - 4;
        d = d < 0 ? 0 : (d > (L - 1) ? (L - 1) : d);
        aL[j] = g_loB[base + d * SLAB];
    }
#pragma unroll
    for (int i = 0; i < 16; ++i) {
        float sL = 0.f, sH = 0.f;
#pragma unroll
        for (int t = 0; t < 9; ++t)  sL = fmaf(aL[i + t], klw(t), sL);
#pragma unroll
        for (int t = 0; t < 15; ++t) sH = fmaf(aH[i + t], khw(t), sH);
        out[base + (d0 + i) * SLAB] = sL - sH;
    }
}

extern "C" void kernel_launch(void* const* d_in, const int* in_sizes, int n_in,
                              void* d_out, int out_size) {
    const float* x = (const float*)d_in[0];
    float* out = (float*)d_out;

    const int smem = (ROWS * PADW + 2 * ROWS * L) * (int)sizeof(float); // 91264B
    static int attr_done = 0;
    if (!attr_done) {
        cudaFuncSetAttribute(pass_wh_kernel,
                             cudaFuncAttributeMaxDynamicSharedMemorySize, smem);
        attr_done = 1;
    }

    pass_wh_kernel<<<320 * 5, 320, smem>>>(x);
    pass_d_kernel<<<2000, 256>>>(out);
}

// round 4
// speedup vs baseline: 1.3235x; 1.0640x over previous
#include <cuda_runtime.h>
#include <cuda_fp16.h>

// ---------------------------------------------------------------------------
// DoG 3D: out = blur(x, sigma=1.0, k=9) - blur(x, sigma=1.6, k=15)
// Separable, replicate boundary. 2 kernels:
//   fused W+H pass (smem 2D tile, f32x2 packed FMA) -> fp16 g_lo/g_hi
//   D pass (half2 loads, f32x2 FMA, fused subtract)  -> out (fp32)
// ---------------------------------------------------------------------------

#define NB 2
#define L 160
#define SLAB (L * L)          // 25600
#define VOL (L * L * L)       // 4096000
#define TOT (NB * VOL)        // 8192000

// fp16 intermediates, declared as __half2 for guaranteed 4B alignment.
__device__ __half2 g_lo2[TOT / 2];
__device__ __half2 g_hi2[TOT / 2];
#define G_LO ((__half*)g_lo2)
#define G_HI ((__half*)g_hi2)

// Normalized 1D gaussian weights (each sums to 1).
#define KL0 1.338302e-04f
#define KL1 4.431861e-03f
#define KL2 5.399113e-02f
#define KL3 2.419714e-01f
#define KL4 3.989435e-01f

#define KH0 1.739620e-05f
#define KH1 2.203730e-04f
#define KH2 1.888900e-03f
#define KH3 1.095520e-02f
#define KH4 4.299160e-02f
#define KH5 1.141557e-01f
#define KH6 2.051009e-01f
#define KH7 2.493392e-01f

__device__ __forceinline__ float klw(int i) {
    const float v[9] = {KL0, KL1, KL2, KL3, KL4, KL3, KL2, KL1, KL0};
    return v[i];
}
__device__ __forceinline__ float khw(int i) {
    const float v[15] = {KH0, KH1, KH2, KH3, KH4, KH5, KH6, KH7,
                         KH6, KH5, KH4, KH3, KH2, KH1, KH0};
    return v[i];
}

// ---------------- packed f32x2 helpers -------------------------------------
typedef unsigned long long u64;

__device__ __forceinline__ u64 pk(float a, float b) {
    u64 r;
    asm("mov.b64 %0, {%1, %2};" : "=l"(r) : "f"(a), "f"(b));
    return r;
}
__device__ __forceinline__ void upk(u64 v, float& a, float& b) {
    asm("mov.b64 {%0, %1}, %2;" : "=f"(a), "=f"(b) : "l"(v));
}
__device__ __forceinline__ void fma2(u64& d, u64 a, u64 b) {
    asm("fma.rn.f32x2 %0, %1, %2, %0;" : "+l"(d) : "l"(a), "l"(b));
}

// ---------------- fused pass: conv along W then H ---------------------------
#define HT 32
#define ROWS (HT + 14)        // 46
#define PADW 176              // 160 + 14 halo, padded

__global__ void __launch_bounds__(320, 2) pass_wh_kernel(const float* __restrict__ x) {
    extern __shared__ float sm[];
    float* s_in = sm;                      // ROWS * PADW
    float* s_lo = sm + ROWS * PADW;        // ROWS * L
    float* s_hi = s_lo + ROWS * L;         // ROWS * L

    const int b = blockIdx.x;
    const int slab = b / 5;                // n*160 + d, 0..319
    const int tile = b % 5;
    const int h0 = tile * HT - 7;
    const int base_g = slab * SLAB;
    const int tid = threadIdx.x;

    // ---- load input tile with replicate clamp in h and w -------------------
    for (int idx = tid; idx < ROWS * 174; idx += 320) {
        const int r = idx / 174;
        const int c = idx % 174;           // c-7 = w
        int h = h0 + r;
        h = h < 0 ? 0 : (h > (L - 1) ? (L - 1) : h);
        int w = c - 7;
        w = w < 0 ? 0 : (w > (L - 1) ? (L - 1) : w);
        s_in[r * PADW + c] = x[base_g + h * L + w];
    }
    __syncthreads();

    // ---- W-conv: warp per row, lane -> 5 outputs (2 packed pairs + 1 scalar)
    {
        const int warp = tid >> 5;
        const int lane = tid & 31;
        const int c0 = lane * 5;
        for (int r = warp; r < ROWS; r += 10) {
            const float* row = &s_in[r * PADW];
            float v[19];
#pragma unroll
            for (int j = 0; j < 19; ++j) v[j] = row[c0 + j];
            u64 p[17];
#pragma unroll
            for (int j = 0; j < 17; ++j) p[j] = pk(v[j], v[j + 1]);

            u64 aH0 = 0, aH1 = 0, aL0 = 0, aL1 = 0;
#pragma unroll
            for (int t = 0; t < 15; ++t) {
                const u64 wh = pk(khw(t), khw(t));
                fma2(aH0, p[t], wh);
                fma2(aH1, p[t + 2], wh);
            }
#pragma unroll
            for (int t = 0; t < 9; ++t) {
                const u64 wl = pk(klw(t), klw(t));
                fma2(aL0, p[t + 3], wl);
                fma2(aL1, p[t + 5], wl);
            }
            float sH4 = 0.f, sL4 = 0.f;
#pragma unroll
            for (int t = 0; t < 15; ++t) sH4 = fmaf(v[4 + t], khw(t), sH4);
#pragma unroll
            for (int t = 0; t < 9; ++t)  sL4 = fmaf(v[7 + t], klw(t), sL4);

            float e0, e1;
            upk(aL0, e0, e1); s_lo[r * L + c0] = e0;     s_lo[r * L + c0 + 1] = e1;
            upk(aL1, e0, e1); s_lo[r * L + c0 + 2] = e0; s_lo[r * L + c0 + 3] = e1;
            s_lo[r * L + c0 + 4] = sL4;
            upk(aH0, e0, e1); s_hi[r * L + c0] = e0;     s_hi[r * L + c0 + 1] = e1;
            upk(aH1, e0, e1); s_hi[r * L + c0 + 2] = e0; s_hi[r * L + c0 + 3] = e1;
            s_hi[r * L + c0 + 4] = sH4;
        }
    }
    __syncthreads();

    // ---- H-conv: w = tid%160, 16 h-outputs/thread, packed along h ----------
    {
        const int w = tid % L;
        const int hh0 = (tid / L) * 16;    // 0 or 16
#pragma unroll
        for (int chk = 0; chk < 2; ++chk) {
            const int i0 = chk * 8;        // 8 outputs per chunk
            // high: rows hh0+i0 .. hh0+i0+21 (22 vals -> 21 packed pairs)
            u64 aH[4] = {0, 0, 0, 0};
            {
                u64 pB[21];
                float prev = s_hi[(hh0 + i0) * L + w];
#pragma unroll
                for (int j = 0; j < 21; ++j) {
                    const float cur = s_hi[(hh0 + i0 + j + 1) * L + w];
                    pB[j] = pk(prev, cur);
                    prev = cur;
                }
#pragma unroll
                for (int t = 0; t < 15; ++t) {
                    const u64 wh = pk(khw(t), khw(t));
                    fma2(aH[0], pB[t], wh);
                    fma2(aH[1], pB[t + 2], wh);
                    fma2(aH[2], pB[t + 4], wh);
                    fma2(aH[3], pB[t + 6], wh);
                }
            }
            // low: rows hh0+i0+3 .. hh0+i0+19 (17 vals -> 16 packed pairs)
            u64 aL[4] = {0, 0, 0, 0};
            {
                u64 pA[16];
                float prev = s_lo[(hh0 + i0 + 3) * L + w];
#pragma unroll
                for (int j = 0; j < 16; ++j) {
                    const float cur = s_lo[(hh0 + i0 + 4 + j) * L + w];
                    pA[j] = pk(prev, cur);
                    prev = cur;
                }
#pragma unroll
                for (int t = 0; t < 9; ++t) {
                    const u64 wl = pk(klw(t), klw(t));
                    fma2(aL[0], pA[t], wl);
                    fma2(aL[1], pA[t + 2], wl);
                    fma2(aL[2], pA[t + 4], wl);
                    fma2(aL[3], pA[t + 6], wl);
                }
            }
            const int ghb = tile * HT + hh0 + i0;
#pragma unroll
            for (int pr = 0; pr < 4; ++pr) {
                float l0, l1, hv0, hv1;
                upk(aL[pr], l0, l1);
                upk(aH[pr], hv0, hv1);
                const int o = base_g + (ghb + pr * 2) * L + w;
                G_LO[o] = __float2half(l0);
                G_HI[o] = __float2half(hv0);
                G_LO[o + L] = __float2half(l1);
                G_HI[o + L] = __float2half(hv1);
            }
        }
    }
}

// ---------------- pass D: conv along D + subtract (w-pairs, half2 loads) ---
__global__ void __launch_bounds__(256) pass_d_kernel(float* __restrict__ out) {
    const int tid = blockIdx.x * 256 + threadIdx.x;  // < 256000
    const int wp = tid % 80;
    const int rest = tid / 80;
    const int h = rest % L;
    const int r2 = rest / L;      // 0..19
    const int seg = r2 % 10;
    const int n = r2 / 10;
    const int base = n * VOL + h * L + wp * 2;
    const int d0 = seg * 16;

#pragma unroll
    for (int ch = 0; ch < 2; ++ch) {
        const int i0 = d0 + ch * 8;       // 8 d-outputs this chunk
        u64 acc[8] = {0, 0, 0, 0, 0, 0, 0, 0};
        // low taps (+klw)
        {
            u64 pA[17];
#pragma unroll
            for (int j = 0; j < 17; ++j) {
                int d = i0 + j - 4;
                d = d < 0 ? 0 : (d > (L - 1) ? (L - 1) : d);
                const float2 f = __half22float2(
                    *(const __half2*)&G_LO[base + d * SLAB]);
                pA[j] = pk(f.x, f.y);
            }
#pragma unroll
            for (int t = 0; t < 9; ++t) {
                const u64 wl = pk(klw(t), klw(t));
#pragma unroll
                for (int i = 0; i < 8; ++i) fma2(acc[i], pA[i + t], wl);
            }
        }
        // high taps with negated weights -> acc = low - high directly
        {
            u64 pB[22];
#pragma unroll
            for (int j = 0; j < 22; ++j) {
                int d = i0 + j - 7;
                d = d < 0 ? 0 : (d > (L - 1) ? (L - 1) : d);
                const float2 f = __half22float2(
                    *(const __half2*)&G_HI[base + d * SLAB]);
                pB[j] = pk(f.x, f.y);
            }
#pragma unroll
            for (int t = 0; t < 15; ++t) {
                const u64 wh = pk(-khw(t), -khw(t));
#pragma unroll
                for (int i = 0; i < 8; ++i) fma2(acc[i], pB[i + t], wh);
            }
        }
#pragma unroll
        for (int i = 0; i < 8; ++i) {
            float a, bq;
            upk(acc[i], a, bq);
            float2 o;
            o.x = a;
            o.y = bq;
            *(float2*)&out[base + (i0 + i) * SLAB] = o;
        }
    }
}

extern "C" void kernel_launch(void* const* d_in, const int* in_sizes, int n_in,
                              void* d_out, int out_size) {
    const float* x = (const float*)d_in[0];
    float* out = (float*)d_out;

    const int smem = (ROWS * PADW + 2 * ROWS * L) * (int)sizeof(float); // 91264B
    static int attr_done = 0;
    if (!attr_done) {
        cudaFuncSetAttribute(pass_wh_kernel,
                             cudaFuncAttributeMaxDynamicSharedMemorySize, smem);
        attr_done = 1;
    }

    pass_wh_kernel<<<320 * 5, 320, smem>>>(x);
    pass_d_kernel<<<1000, 256>>>(out);
}